// round 4
// baseline (speedup 1.0000x reference)
#include <cuda_runtime.h>
#include <math.h>

#define G        512
#define S        32
#define PTS      8
#define SEGS_PER (PTS - 1)           // 7
#define NSEG     (S * SEGS_PER)      // 224
#define TILE     16
#define NTHREADS 128                 // 16 x 8, each thread does 2 pixels

// ---------------------------------------------------------------------------
// One 16x16 tile per 128-thread block, 2 pixels per thread.
// Phase A: stage clamped pixel-space stroke points (512 floats) + per-stroke
//          {r=2t, sc=1/(4t^2)} into SMEM. One LDG.128 per thread.
// Phase B: per-segment constants from SMEM, conservative capsule cull vs tile
//          center, compact survivors (float4 + float2).
// Phase C: per-pixel min of scaled squared distance over survivors; rows
//          ty and ty+8 share segment data and partial algebra.
// ---------------------------------------------------------------------------
__global__ void __launch_bounds__(NTHREADS)
render_kernel(const float* __restrict__ strokes,
              const float* __restrict__ thick,
              float* __restrict__ out) {
    __shared__ float  s_pts[S * PTS * 2];   // clamped * 512 coords
    __shared__ float2 s_t[S];               // {r = 2t, sc = 1/(4t^2)}
    __shared__ float4 s_a[NSEG];            // vx, vy, ex, ey
    __shared__ float2 s_b[NSEG];            // invd2, scale
    __shared__ int    s_n;

    const int tid = threadIdx.x;
    if (tid == 0) s_n = 0;

    // ---- Phase A: stage inputs (512 floats = 128 * float4) ----
    {
        float4 v = ((const float4*)strokes)[tid];
        float4 c;
        c.x = __saturatef(v.x) * (float)G;
        c.y = __saturatef(v.y) * (float)G;
        c.z = __saturatef(v.z) * (float)G;
        c.w = __saturatef(v.w) * (float)G;
        ((float4*)s_pts)[tid] = c;
        if (tid < S) {
            float t = fmaxf(fmaf(thick[tid], 2.0f, 0.5f), 0.5f);
            float r = 2.0f * t;
            s_t[tid] = make_float2(r, __fdividef(1.0f, r * r));
        }
    }
    __syncthreads();

    const int ti = blockIdx.y * TILE;   // row (out stride G)
    const int tj = blockIdx.x * TILE;   // col (contiguous)

    const float cx   = (float)ti + (TILE - 1) * 0.5f;
    const float cy   = (float)tj + (TILE - 1) * 0.5f;
    const float RMAX = (TILE - 1) * 0.5f * 1.41421356f + 1.0f;

    // ---- Phase B: cull 224 segments (each thread handles up to 2) ----
    #pragma unroll
    for (int seg = tid; seg < NSEG; seg += NTHREADS) {
        const int s = seg / SEGS_PER;
        // point index: (s*PTS + k)*2 where k = seg - 7s  ->  (seg + s)*2
        const int base = (seg + s) * 2;
        float2 vv = *(const float2*)(s_pts + base);
        float2 ww = *(const float2*)(s_pts + base + 2);

        float ex = ww.x - vv.x;
        float ey = ww.y - vv.y;
        float d2 = ex * ex + ey * ey;
        float invd2 = __fdividef(1.0f, d2 + 1e-5f);
        float2 rs = s_t[s];

        float dx  = cx - vv.x;
        float dy  = cy - vv.y;
        float dot = dx * ex + dy * ey;
        float fr  = __saturatef(dot * invd2);
        float ddx = fmaf(-fr, ex, dx);
        float ddy = fmaf(-fr, ey, dy);
        float dq  = ddx * ddx + ddy * ddy;
        float thr = rs.x + RMAX;
        if (dq <= thr * thr) {
            int p = atomicAdd(&s_n, 1);
            s_a[p] = make_float4(vv.x, vv.y, ex, ey);
            s_b[p] = make_float2(invd2, rs.y);
        }
    }
    __syncthreads();

    // ---- Phase C: 2 pixels per thread (rows ty and ty+8) ----
    const int tx = tid & (TILE - 1);
    const int ty = tid >> 4;
    const float px0 = (float)(ti + ty);
    const float py  = (float)(tj + tx);
    const int n = s_n;

    float m0 = 1e30f;
    float m1 = 1e30f;
    #pragma unroll 2
    for (int q = 0; q < n; q++) {
        float4 a = s_a[q];
        float2 b = s_b[q];
        float dx0  = px0 - a.x;
        float dx1  = dx0 + 8.0f;
        float dy   = py - a.y;
        float dyey = dy * a.w;
        float dot0 = fmaf(dx0, a.z, dyey);
        float dot1 = fmaf(8.0f, a.z, dot0);
        float fr0  = __saturatef(dot0 * b.x);
        float fr1  = __saturatef(dot1 * b.x);
        float ddx0 = fmaf(-fr0, a.z, dx0);
        float ddy0 = fmaf(-fr0, a.w, dy);
        float ddx1 = fmaf(-fr1, a.z, dx1);
        float ddy1 = fmaf(-fr1, a.w, dy);
        float dq0  = fmaf(ddx0, ddx0, ddy0 * ddy0);
        float dq1  = fmaf(ddx1, ddx1, ddy1 * ddy1);
        m0 = fminf(m0, dq0 * b.y);
        m1 = fminf(m1, dq1 * b.y);
    }

    float* o = out + (ti + ty) * G + (tj + tx);
    o[0]     = fminf(sqrtf(m0), 1.0f);
    o[8 * G] = fminf(sqrtf(m1), 1.0f);
}

extern "C" void kernel_launch(void* const* d_in, const int* in_sizes, int n_in,
                              void* d_out, int out_size) {
    // metadata order: strokes [32,8,2] f32 (512 elems), thicknesses [32] f32.
    const float* strokes = (const float*)d_in[0];
    const float* thick   = (const float*)d_in[1];
    if (n_in >= 2 && in_sizes[0] == S && in_sizes[1] == S * PTS * 2) {
        strokes = (const float*)d_in[1];
        thick   = (const float*)d_in[0];
    }
    float* out = (float*)d_out;

    dim3 block(NTHREADS);
    dim3 grid(G / TILE, G / TILE);
    render_kernel<<<grid, block>>>(strokes, thick, out);
}